// round 1
// baseline (speedup 1.0000x reference)
#include <cuda_runtime.h>
#include <math.h>

// Problem constants
#define B   16
#define L   512
#define D   512
#define NH  8
#define HD  64
#define T   17
#define CYC 2
#define BL  (B * L)   // 8192

// ---------------------------------------------------------------------------
// Scratch buffers (device globals — no allocation allowed in kernel_launch)
// ---------------------------------------------------------------------------
__device__ float g_e[BL * D];
__device__ float g_h[BL * D];
__device__ float g_s[B * D];
__device__ float g_q[BL * D];
__device__ float g_k[BL * D];
__device__ float g_v[BL * D];
__device__ float g_ke[BL * D];
__device__ float g_ve[BL * D];
__device__ float g_ctx[BL * D];
__device__ float g_a[BL * D];
__device__ float g_kr[BL * D];
__device__ float g_vr[BL * D];
__device__ float g_ks[B * D];
__device__ float g_vs[B * D];
__device__ float g_qsr[B * D];
__device__ float g_ksr[B * D];
__device__ float g_vsr[B * D];
__device__ float g_ctxs[B * D];
__device__ float g_r[B * D];

// ---------------------------------------------------------------------------
// Embedding + copy:  e[b,l,:] = char_emb[tok]; h = e
// ---------------------------------------------------------------------------
__global__ void embed_kernel(const int* __restrict__ tokens,
                             const float* __restrict__ emb,
                             float* __restrict__ e, float* __restrict__ h) {
    int idx = blockIdx.x * 256 + threadIdx.x;     // BL*D threads
    int row = idx / D;
    int d   = idx - row * D;
    int tok = tokens[row];
    float v = emb[tok * D + d];
    e[idx] = v;
    h[idx] = v;
}

// s[b,d] = mean over l of e[b,l,d]
__global__ void smean_kernel(const float* __restrict__ e, float* __restrict__ s) {
    int idx = blockIdx.x * 256 + threadIdx.x;     // B*D threads
    int b = idx >> 9;
    int d = idx & 511;
    const float* p = e + (b << 9) * D + d;
    float acc = 0.f;
    #pragma unroll 8
    for (int l = 0; l < L; l++) acc += p[l * D];
    s[idx] = acc * (1.f / (float)L);
}

// ---------------------------------------------------------------------------
// SGEMM: C[M,512] = A[M,512] @ W[512,512] + bias   (K = N = 512 fixed)
// 128x128 tile, BK=8, 8x8 per-thread, 256 threads
// ---------------------------------------------------------------------------
__global__ void __launch_bounds__(256)
sgemm_bias(int M, const float* __restrict__ A, const float* __restrict__ W,
           const float* __restrict__ bias, float* __restrict__ C) {
    const int K = 512, N = 512;
    const int BM = 128, BN = 128, BK = 8, TM = 8, TN = 8;
    __shared__ float As[BK][BM];
    __shared__ float Ws[BK][BN];

    int tid  = threadIdx.x;
    int row0 = blockIdx.y * BM;
    int col0 = blockIdx.x * BN;
    int tx = tid & 15;          // 0..15
    int ty = tid >> 4;          // 0..15

    int a_row = tid >> 1;            // 0..127
    int a_col = (tid & 1) << 2;      // 0 or 4
    int w_row = tid >> 5;            // 0..7
    int w_col = (tid & 31) << 2;     // 0..124

    float acc[TM][TN];
    #pragma unroll
    for (int i = 0; i < TM; i++)
        #pragma unroll
        for (int j = 0; j < TN; j++) acc[i][j] = 0.f;

    bool a_ok = (row0 + a_row) < M;
    const float* Aptr = A + (row0 + a_row) * K + a_col;
    const float* Wptr = W + w_row * N + col0 + w_col;

    for (int k0 = 0; k0 < K; k0 += BK) {
        float4 av = a_ok ? *(const float4*)(Aptr + k0)
                         : make_float4(0.f, 0.f, 0.f, 0.f);
        As[a_col + 0][a_row] = av.x;
        As[a_col + 1][a_row] = av.y;
        As[a_col + 2][a_row] = av.z;
        As[a_col + 3][a_row] = av.w;
        *(float4*)&Ws[w_row][w_col] = *(const float4*)(Wptr + k0 * N);
        __syncthreads();

        #pragma unroll
        for (int kk = 0; kk < BK; kk++) {
            float4 a0 = *(float4*)&As[kk][ty * TM];
            float4 a1 = *(float4*)&As[kk][ty * TM + 4];
            float4 w0 = *(float4*)&Ws[kk][tx * TN];
            float4 w1 = *(float4*)&Ws[kk][tx * TN + 4];
            float ar[TM] = {a0.x, a0.y, a0.z, a0.w, a1.x, a1.y, a1.z, a1.w};
            float wr[TN] = {w0.x, w0.y, w0.z, w0.w, w1.x, w1.y, w1.z, w1.w};
            #pragma unroll
            for (int i = 0; i < TM; i++)
                #pragma unroll
                for (int j = 0; j < TN; j++)
                    acc[i][j] = fmaf(ar[i], wr[j], acc[i][j]);
        }
        __syncthreads();
    }

    #pragma unroll
    for (int i = 0; i < TM; i++) {
        int r = row0 + ty * TM + i;
        if (r < M) {
            #pragma unroll
            for (int j = 0; j < TN; j += 4) {
                int c = col0 + tx * TN + j;
                float4 o;
                o.x = acc[i][j + 0] + bias[c + 0];
                o.y = acc[i][j + 1] + bias[c + 1];
                o.z = acc[i][j + 2] + bias[c + 2];
                o.w = acc[i][j + 3] + bias[c + 3];
                *(float4*)(C + r * 512 + c) = o;
            }
        }
    }
}

// ---------------------------------------------------------------------------
// sat attention: per token, 5 keys (h_last, h, h_next, e, s_mean)
// grid = BL blocks, 256 threads = 8 warps = 8 heads, 2 dims/lane
// ---------------------------------------------------------------------------
__global__ void sat_attn(const float* __restrict__ Q,  const float* __restrict__ Kh,
                         const float* __restrict__ Vh, const float* __restrict__ Ke,
                         const float* __restrict__ Ve, const float* __restrict__ Ks,
                         const float* __restrict__ Vs, float* __restrict__ ctx) {
    int t = blockIdx.x;
    int b = t >> 9;
    int l = t & 511;
    int head = threadIdx.x >> 5;
    int lane = threadIdx.x & 31;
    int d0 = head * HD + lane;            // dims d0 and d0+32
    int base = t * D;
    int r0 = (b << 9) + ((l + 1) & 511);          // h_last = roll(h,-1)
    int r2 = (b << 9) + (l == 0 ? (L - 1) : 0);   // h_next

    float q0 = Q[base + d0], q1 = Q[base + d0 + 32];
    const float* kp[5] = { Kh + r0 * D + d0, Kh + base + d0, Kh + r2 * D + d0,
                           Ke + base + d0,   Ks + b * D + d0 };
    const float* vp[5] = { Vh + r0 * D + d0, Vh + base + d0, Vh + r2 * D + d0,
                           Ve + base + d0,   Vs + b * D + d0 };
    float sc[5];
    #pragma unroll
    for (int i = 0; i < 5; i++) {
        float p = q0 * kp[i][0] + q1 * kp[i][32];
        #pragma unroll
        for (int o = 16; o > 0; o >>= 1) p += __shfl_xor_sync(0xffffffffu, p, o);
        sc[i] = p * 0.125f;   // / sqrt(64)
    }
    float m = sc[0];
    #pragma unroll
    for (int i = 1; i < 5; i++) m = fmaxf(m, sc[i]);
    float den = 0.f;
    #pragma unroll
    for (int i = 0; i < 5; i++) { sc[i] = expf(sc[i] - m); den += sc[i]; }
    float inv = 1.f / den;
    float o0 = 0.f, o1 = 0.f;
    #pragma unroll
    for (int i = 0; i < 5; i++) {
        o0 = fmaf(sc[i], vp[i][0],  o0);
        o1 = fmaf(sc[i], vp[i][32], o1);
    }
    ctx[base + d0]      = o0 * inv;
    ctx[base + d0 + 32] = o1 * inv;
}

// ---------------------------------------------------------------------------
// rel attention: per (batch, head), 513 keys = [s] + h[0..511]
// ---------------------------------------------------------------------------
__global__ void rel_attn(const float* __restrict__ Qs,  const float* __restrict__ Ksr,
                         const float* __restrict__ Kr,  const float* __restrict__ Vsr,
                         const float* __restrict__ Vr,  float* __restrict__ ctxs) {
    __shared__ float sc[513];
    __shared__ float red[256];
    __shared__ float qsh[HD];
    int b    = blockIdx.x >> 3;
    int head = blockIdx.x & 7;
    int tid  = threadIdx.x;
    int off  = head * HD;

    if (tid < HD) qsh[tid] = Qs[b * D + off + tid];
    __syncthreads();

    for (int k = tid; k < 513; k += 256) {
        const float* kv = (k == 0) ? (Ksr + b * D + off)
                                   : (Kr + ((b << 9) + k - 1) * D + off);
        float p = 0.f;
        #pragma unroll
        for (int d = 0; d < HD; d++) p = fmaf(qsh[d], kv[d], p);
        sc[k] = p * 0.125f;
    }
    __syncthreads();

    float m = -1e30f;
    for (int k = tid; k < 513; k += 256) m = fmaxf(m, sc[k]);
    red[tid] = m; __syncthreads();
    for (int st = 128; st > 0; st >>= 1) {
        if (tid < st) red[tid] = fmaxf(red[tid], red[tid + st]);
        __syncthreads();
    }
    m = red[0];
    __syncthreads();

    float dsum = 0.f;
    for (int k = tid; k < 513; k += 256) {
        float e_ = expf(sc[k] - m);
        sc[k] = e_;
        dsum += e_;
    }
    red[tid] = dsum; __syncthreads();
    for (int st = 128; st > 0; st >>= 1) {
        if (tid < st) red[tid] += red[tid + st];
        __syncthreads();
    }
    float inv = 1.f / red[0];

    if (tid < HD) {
        float acc = sc[0] * Vsr[b * D + off + tid];
        for (int k = 1; k < 513; k++)
            acc = fmaf(sc[k], Vr[((b << 9) + k - 1) * D + off + tid], acc);
        ctxs[b * D + off + tid] = acc * inv;
    }
}

// ---------------------------------------------------------------------------
// relu + LayerNorm over rows of width 512 (eps = 1e-12)
// ---------------------------------------------------------------------------
__global__ void relu_ln(const float* __restrict__ x, const float* __restrict__ w,
                        const float* __restrict__ bb, float* __restrict__ out) {
    __shared__ float red[256];
    int row = blockIdx.x;
    int tid = threadIdx.x;
    float v0 = fmaxf(x[row * D + tid],       0.f);
    float v1 = fmaxf(x[row * D + tid + 256], 0.f);
    red[tid] = v0 + v1;
    __syncthreads();
    for (int st = 128; st > 0; st >>= 1) {
        if (tid < st) red[tid] += red[tid + st];
        __syncthreads();
    }
    float mean = red[0] * (1.f / 512.f);
    __syncthreads();
    float d0 = v0 - mean, d1 = v1 - mean;
    red[tid] = d0 * d0 + d1 * d1;
    __syncthreads();
    for (int st = 128; st > 0; st >>= 1) {
        if (tid < st) red[tid] += red[tid + st];
        __syncthreads();
    }
    float inv = rsqrtf(red[0] * (1.f / 512.f) + 1e-12f);
    out[row * D + tid]       = w[tid]       * d0 * inv + bb[tid];
    out[row * D + tid + 256] = w[tid + 256] * d1 * inv + bb[tid + 256];
}

// ---------------------------------------------------------------------------
// logits = h @ ofc_w[512,17] + ofc_b   — one warp per row
// ---------------------------------------------------------------------------
__global__ void final_logits(const float* __restrict__ h, const float* __restrict__ W,
                             const float* __restrict__ bias, float* __restrict__ out) {
    __shared__ float Wsh[512 * T];
    int tid = threadIdx.x;
    for (int i = tid; i < 512 * T; i += 256) Wsh[i] = W[i];
    __syncthreads();
    int warp = tid >> 5, lane = tid & 31;
    int row = blockIdx.x * 8 + warp;
    float acc[T];
    #pragma unroll
    for (int t = 0; t < T; t++) acc[t] = 0.f;
    const float* hr = h + row * D;
    for (int k = lane; k < D; k += 32) {
        float a = hr[k];
        #pragma unroll
        for (int t = 0; t < T; t++) acc[t] = fmaf(a, Wsh[k * T + t], acc[t]);
    }
    #pragma unroll
    for (int t = 0; t < T; t++)
        #pragma unroll
        for (int o = 16; o > 0; o >>= 1)
            acc[t] += __shfl_xor_sync(0xffffffffu, acc[t], o);
    if (lane == 0) {
        #pragma unroll
        for (int t = 0; t < T; t++) out[row * T + t] = acc[t] + bias[t];
    }
}

// ---------------------------------------------------------------------------
// Launch
// ---------------------------------------------------------------------------
extern "C" void kernel_launch(void* const* d_in, const int* in_sizes, int n_in,
                              void* d_out, int out_size) {
    (void)in_sizes; (void)n_in; (void)out_size;
    const int*   tokens  = (const int*)  d_in[0];
    const float* emb     = (const float*)d_in[4];
    const float* sat_qw  = (const float*)d_in[5];
    const float* sat_qb  = (const float*)d_in[6];
    const float* sat_kw  = (const float*)d_in[7];
    const float* sat_kb  = (const float*)d_in[8];
    const float* sat_vw  = (const float*)d_in[9];
    const float* sat_vb  = (const float*)d_in[10];
    const float* sat_ow  = (const float*)d_in[11];
    const float* sat_ob  = (const float*)d_in[12];
    const float* rel_qw  = (const float*)d_in[13];
    const float* rel_qb  = (const float*)d_in[14];
    const float* rel_kw  = (const float*)d_in[15];
    const float* rel_kb  = (const float*)d_in[16];
    const float* rel_vw  = (const float*)d_in[17];
    const float* rel_vb  = (const float*)d_in[18];
    const float* rel_ow  = (const float*)d_in[19];
    const float* rel_ob  = (const float*)d_in[20];
    const float* ln_sw   = (const float*)d_in[21];
    const float* ln_sb   = (const float*)d_in[22];
    const float* ln_rw   = (const float*)d_in[23];
    const float* ln_rb   = (const float*)d_in[24];
    const float* ofc_w   = (const float*)d_in[25];
    const float* ofc_b   = (const float*)d_in[26];
    float* out = (float*)d_out;

    float *e, *h, *s, *q, *k, *v, *ke, *ve, *ctx, *a, *kr, *vr;
    float *ks, *vs, *qsr, *ksr, *vsr, *ctxs, *r;
    cudaGetSymbolAddress((void**)&e,    g_e);
    cudaGetSymbolAddress((void**)&h,    g_h);
    cudaGetSymbolAddress((void**)&s,    g_s);
    cudaGetSymbolAddress((void**)&q,    g_q);
    cudaGetSymbolAddress((void**)&k,    g_k);
    cudaGetSymbolAddress((void**)&v,    g_v);
    cudaGetSymbolAddress((void**)&ke,   g_ke);
    cudaGetSymbolAddress((void**)&ve,   g_ve);
    cudaGetSymbolAddress((void**)&ctx,  g_ctx);
    cudaGetSymbolAddress((void**)&a,    g_a);
    cudaGetSymbolAddress((void**)&kr,   g_kr);
    cudaGetSymbolAddress((void**)&vr,   g_vr);
    cudaGetSymbolAddress((void**)&ks,   g_ks);
    cudaGetSymbolAddress((void**)&vs,   g_vs);
    cudaGetSymbolAddress((void**)&qsr,  g_qsr);
    cudaGetSymbolAddress((void**)&ksr,  g_ksr);
    cudaGetSymbolAddress((void**)&vsr,  g_vsr);
    cudaGetSymbolAddress((void**)&ctxs, g_ctxs);
    cudaGetSymbolAddress((void**)&r,    g_r);

    dim3 gb(4, BL / 128);   // big GEMM: M = 8192
    dim3 gs(4, 1);          // small GEMM: M = 16

    embed_kernel<<<BL * D / 256, 256>>>(tokens, emb, e, h);
    smean_kernel<<<B * D / 256, 256>>>(e, s);

    // e-projections (constant across cycles: e and weights never change)
    sgemm_bias<<<gb, 256>>>(BL, e, sat_kw, sat_kb, ke);
    sgemm_bias<<<gb, 256>>>(BL, e, sat_vw, sat_vb, ve);

    for (int c = 0; c < CYC; c++) {
        // sat projections of h and s
        sgemm_bias<<<gb, 256>>>(BL, h, sat_qw, sat_qb, q);
        sgemm_bias<<<gb, 256>>>(BL, h, sat_kw, sat_kb, k);
        sgemm_bias<<<gb, 256>>>(BL, h, sat_vw, sat_vb, v);
        sgemm_bias<<<gs, 256>>>(B,  s, sat_kw, sat_kb, ks);
        sgemm_bias<<<gs, 256>>>(B,  s, sat_vw, sat_vb, vs);

        sat_attn<<<BL, 256>>>(q, k, v, ke, ve, ks, vs, ctx);
        sgemm_bias<<<gb, 256>>>(BL, ctx, sat_ow, sat_ob, a);
        relu_ln<<<BL, 256>>>(a, ln_sw, ln_sb, h);

        // rel projections
        sgemm_bias<<<gb, 256>>>(BL, h, rel_kw, rel_kb, kr);
        sgemm_bias<<<gb, 256>>>(BL, h, rel_vw, rel_vb, vr);
        sgemm_bias<<<gs, 256>>>(B,  s, rel_qw, rel_qb, qsr);
        sgemm_bias<<<gs, 256>>>(B,  s, rel_kw, rel_kb, ksr);
        sgemm_bias<<<gs, 256>>>(B,  s, rel_vw, rel_vb, vsr);

        rel_attn<<<B * NH, 256>>>(qsr, ksr, kr, vsr, vr, ctxs);
        sgemm_bias<<<gs, 256>>>(B, ctxs, rel_ow, rel_ob, r);
        relu_ln<<<B, 256>>>(r, ln_rw, ln_rb, s);
    }

    final_logits<<<BL / 8, 256>>>(h, ofc_w, ofc_b, out);
}

// round 3
// speedup vs baseline: 1.4923x; 1.4923x over previous
#include <cuda_runtime.h>
#include <cuda_bf16.h>
#include <cstdint>
#include <math.h>

// Problem constants
#define B   16
#define L   512
#define D   512
#define NH  8
#define HD  64
#define T   17
#define CYC 2
#define BL  (B * L)   // 8192
#define DD  (D * D)

// ---------------------------------------------------------------------------
// Scratch (device globals — allocation is forbidden in kernel_launch)
// ---------------------------------------------------------------------------
__device__ float g_e[BL * D];
__device__ float g_h[BL * D];
__device__ float g_s[B * D];
__device__ float g_q[BL * D];
__device__ float g_k[BL * D];
__device__ float g_v[BL * D];
__device__ float g_ke[BL * D];
__device__ float g_ve[BL * D];
__device__ float g_ctx[BL * D];
__device__ float g_a[BL * D];
__device__ float g_kr[BL * D];
__device__ float g_vr[BL * D];
__device__ float g_ks[B * D];
__device__ float g_vs[B * D];
__device__ float g_qsr[B * D];
__device__ float g_ksr[B * D];
__device__ float g_vsr[B * D];
__device__ float g_ctxs[B * D];
__device__ float g_r[B * D];

// bf16 split buffers (16B aligned for cp.async.cg .. 16)
__device__ __align__(16) __nv_bfloat16 g_ahi[BL * D];
__device__ __align__(16) __nv_bfloat16 g_alo[BL * D];
__device__ __align__(16) __nv_bfloat16 g_whi[8 * DD];   // transposed [N][K]
__device__ __align__(16) __nv_bfloat16 g_wlo[8 * DD];

// ---------------------------------------------------------------------------
// Embedding + copy
// ---------------------------------------------------------------------------
__global__ void embed_kernel(const int* __restrict__ tokens,
                             const float* __restrict__ emb,
                             float* __restrict__ e, float* __restrict__ h) {
    int idx = blockIdx.x * 256 + threadIdx.x;
    int row = idx / D;
    int d   = idx - row * D;
    int tok = tokens[row];
    float v = emb[tok * D + d];
    e[idx] = v;
    h[idx] = v;
}

__global__ void smean_kernel(const float* __restrict__ e, float* __restrict__ s) {
    int idx = blockIdx.x * 256 + threadIdx.x;
    int b = idx >> 9;
    int d = idx & 511;
    const float* p = e + (b << 9) * D + d;
    float acc = 0.f;
    #pragma unroll 8
    for (int l = 0; l < L; l++) acc += p[l * D];
    s[idx] = acc * (1.f / (float)L);
}

// ---------------------------------------------------------------------------
// Split fp32 activation -> bf16 hi/lo
// ---------------------------------------------------------------------------
__global__ void asplit(const float* __restrict__ x,
                       __nv_bfloat16* __restrict__ hi,
                       __nv_bfloat16* __restrict__ lo) {
    int i = blockIdx.x * 256 + threadIdx.x;
    float v = x[i];
    __nv_bfloat16 h = __float2bfloat16_rn(v);
    hi[i] = h;
    lo[i] = __float2bfloat16_rn(v - __bfloat162float(h));
}

// Split + transpose weight: W[K][N] fp32 -> Wt_hi/lo[N][K] bf16
__global__ void wsplit(const float* __restrict__ W,
                       __nv_bfloat16* __restrict__ hi,
                       __nv_bfloat16* __restrict__ lo) {
    __shared__ float t[32][33];
    int bx = blockIdx.x, by = blockIdx.y;   // bx: n-tile, by: k-tile
    int x = threadIdx.x, y = threadIdx.y;   // 32 x 8
    #pragma unroll
    for (int j = 0; j < 32; j += 8)
        t[y + j][x] = W[(by * 32 + y + j) * 512 + bx * 32 + x];
    __syncthreads();
    #pragma unroll
    for (int j = 0; j < 32; j += 8) {
        float v = t[x][y + j];              // = W[by*32+x][bx*32+y+j]
        int n = bx * 32 + y + j;
        int k = by * 32 + x;
        __nv_bfloat16 hv = __float2bfloat16_rn(v);
        hi[n * 512 + k] = hv;
        lo[n * 512 + k] = __float2bfloat16_rn(v - __bfloat162float(hv));
    }
}

// ---------------------------------------------------------------------------
// Tensor-core GEMM: C[8192,512] = A[8192,512] @ W[512,512] + bias
//   A, W in split bf16; W stored transposed [N][K].
//   mma.sync m16n8k16 row.col, f32 accumulate.
//   3-term split: hi*hi + hi*lo + lo*hi.
// Block 128x128x32, 256 threads (8 warps, warp tile 64x32), cp.async 2-stage.
// ---------------------------------------------------------------------------
#define SMEM_STAGE 20480   // bf16 elements per stage (A hi/lo + B hi/lo)
#define SMEM_BYTES (2 * SMEM_STAGE * 2)

__device__ __forceinline__ void mma16816(float* d, const uint32_t* a,
                                         const uint32_t* b) {
    asm volatile("mma.sync.aligned.m16n8k16.row.col.f32.bf16.bf16.f32 "
                 "{%0,%1,%2,%3}, {%4,%5,%6,%7}, {%8,%9}, {%0,%1,%2,%3};"
                 : "+f"(d[0]), "+f"(d[1]), "+f"(d[2]), "+f"(d[3])
                 : "r"(a[0]), "r"(a[1]), "r"(a[2]), "r"(a[3]),
                   "r"(b[0]), "r"(b[1]));
}

__global__ void __launch_bounds__(256)
mma_gemm(const __nv_bfloat16* __restrict__ Ahi, const __nv_bfloat16* __restrict__ Alo,
         const __nv_bfloat16* __restrict__ Whi, const __nv_bfloat16* __restrict__ Wlo,
         const float* __restrict__ bias, float* __restrict__ C) {
    extern __shared__ __nv_bfloat16 sm[];
    const int tid  = threadIdx.x;
    const int lane = tid & 31;
    const int warp = tid >> 5;
    const int wm = warp >> 2;        // 0..1
    const int wn = warp & 3;         // 0..3
    const int m0 = blockIdx.y * 128;
    const int n0 = blockIdx.x * 128;

    float acc[4][4][4];
    #pragma unroll
    for (int i = 0; i < 4; i++)
        #pragma unroll
        for (int j = 0; j < 4; j++)
            #pragma unroll
            for (int t = 0; t < 4; t++) acc[i][j][t] = 0.f;

    uint32_t smbase = (uint32_t)__cvta_generic_to_shared(sm);

    auto load_stage = [&](int s, int k0) {
        uint32_t base = smbase + (uint32_t)(s * SMEM_STAGE * 2);
        #pragma unroll
        for (int i = 0; i < 2; i++) {
            int id  = tid + i * 256;
            int row = id >> 2;
            int qc  = (id & 3) << 3;            // bf16 col offset (8 per 16B)
            uint32_t so = base + (uint32_t)((row * 40 + qc) * 2);
            const __nv_bfloat16* ga = Ahi + (m0 + row) * 512 + k0 + qc;
            const __nv_bfloat16* gb = Alo + (m0 + row) * 512 + k0 + qc;
            const __nv_bfloat16* gc = Whi + (n0 + row) * 512 + k0 + qc;
            const __nv_bfloat16* gd = Wlo + (n0 + row) * 512 + k0 + qc;
            asm volatile("cp.async.cg.shared.global [%0], [%1], 16;" :: "r"(so),               "l"(ga));
            asm volatile("cp.async.cg.shared.global [%0], [%1], 16;" :: "r"(so + 5120u * 2u),  "l"(gb));
            asm volatile("cp.async.cg.shared.global [%0], [%1], 16;" :: "r"(so + 10240u * 2u), "l"(gc));
            asm volatile("cp.async.cg.shared.global [%0], [%1], 16;" :: "r"(so + 15360u * 2u), "l"(gd));
        }
    };

    load_stage(0, 0);
    asm volatile("cp.async.commit_group;");

    const int r = lane >> 2;
    const int c = (lane & 3) << 1;

    #pragma unroll 1
    for (int it = 0; it < 16; it++) {
        if (it < 15) {
            load_stage((it + 1) & 1, (it + 1) * 32);
            asm volatile("cp.async.commit_group;");
            asm volatile("cp.async.wait_group 1;");
        } else {
            asm volatile("cp.async.wait_group 0;");
        }
        __syncthreads();

        const __nv_bfloat16* A_h = sm + (it & 1) * SMEM_STAGE;
        const __nv_bfloat16* A_l = A_h + 5120;
        const __nv_bfloat16* B_h = A_h + 10240;
        const __nv_bfloat16* B_l = A_h + 15360;

        #pragma unroll
        for (int ks = 0; ks < 2; ks++) {
            uint32_t ah[4][4], al[4][4], bh[4][2], bl[4][2];
            #pragma unroll
            for (int mt = 0; mt < 4; mt++) {
                int row = wm * 64 + mt * 16 + r;
                int col = ks * 16 + c;
                const __nv_bfloat16* p = A_h + row * 40 + col;
                ah[mt][0] = *(const uint32_t*)p;
                ah[mt][1] = *(const uint32_t*)(p + 8 * 40);
                ah[mt][2] = *(const uint32_t*)(p + 8);
                ah[mt][3] = *(const uint32_t*)(p + 8 * 40 + 8);
                const __nv_bfloat16* pl = A_l + row * 40 + col;
                al[mt][0] = *(const uint32_t*)pl;
                al[mt][1] = *(const uint32_t*)(pl + 8 * 40);
                al[mt][2] = *(const uint32_t*)(pl + 8);
                al[mt][3] = *(const uint32_t*)(pl + 8 * 40 + 8);
            }
            #pragma unroll
            for (int nt = 0; nt < 4; nt++) {
                int n = wn * 32 + nt * 8 + r;
                int k = ks * 16 + c;
                const __nv_bfloat16* p = B_h + n * 40 + k;
                bh[nt][0] = *(const uint32_t*)p;
                bh[nt][1] = *(const uint32_t*)(p + 8);
                const __nv_bfloat16* pl = B_l + n * 40 + k;
                bl[nt][0] = *(const uint32_t*)pl;
                bl[nt][1] = *(const uint32_t*)(pl + 8);
            }
            #pragma unroll
            for (int mt = 0; mt < 4; mt++)
                #pragma unroll
                for (int nt = 0; nt < 4; nt++) {
                    mma16816(acc[mt][nt], ah[mt], bh[nt]);
                    mma16816(acc[mt][nt], ah[mt], bl[nt]);
                    mma16816(acc[mt][nt], al[mt], bh[nt]);
                }
        }
        __syncthreads();
    }

    // Epilogue: + bias
    #pragma unroll
    for (int mt = 0; mt < 4; mt++) {
        #pragma unroll
        for (int nt = 0; nt < 4; nt++) {
            int row = m0 + wm * 64 + mt * 16 + r;
            int col = n0 + wn * 32 + nt * 8 + c;
            float b0 = bias[col], b1 = bias[col + 1];
            float2 v0 = make_float2(acc[mt][nt][0] + b0, acc[mt][nt][1] + b1);
            float2 v1 = make_float2(acc[mt][nt][2] + b0, acc[mt][nt][3] + b1);
            *(float2*)(C + row * 512 + col)       = v0;
            *(float2*)(C + (row + 8) * 512 + col) = v1;
        }
    }
}

// ---------------------------------------------------------------------------
// Small GEMM: C[16,512] = A[16,512] @ W[512,512] + bias (fp32, grid=8)
// ---------------------------------------------------------------------------
__global__ void __launch_bounds__(256)
sgemm16(const float* __restrict__ A, const float* __restrict__ W,
        const float* __restrict__ bias, float* __restrict__ C) {
    __shared__ float As[16][512];
    int tid = threadIdx.x;
    for (int i = tid; i < 16 * 512; i += 256) As[i >> 9][i & 511] = A[i];
    __syncthreads();
    int c  = (blockIdx.x << 6) + (tid & 63);
    int rg = (tid >> 6) << 2;
    float a0 = 0.f, a1 = 0.f, a2 = 0.f, a3 = 0.f;
    #pragma unroll 4
    for (int k = 0; k < 512; k++) {
        float w = W[k * 512 + c];
        a0 = fmaf(As[rg + 0][k], w, a0);
        a1 = fmaf(As[rg + 1][k], w, a1);
        a2 = fmaf(As[rg + 2][k], w, a2);
        a3 = fmaf(As[rg + 3][k], w, a3);
    }
    float b = bias[c];
    C[(rg + 0) * 512 + c] = a0 + b;
    C[(rg + 1) * 512 + c] = a1 + b;
    C[(rg + 2) * 512 + c] = a2 + b;
    C[(rg + 3) * 512 + c] = a3 + b;
}

// ---------------------------------------------------------------------------
// sat attention: 5 keys per token
// ---------------------------------------------------------------------------
__global__ void sat_attn(const float* __restrict__ Q,  const float* __restrict__ Kh,
                         const float* __restrict__ Vh, const float* __restrict__ Ke,
                         const float* __restrict__ Ve, const float* __restrict__ Ks,
                         const float* __restrict__ Vs, float* __restrict__ ctx) {
    int t = blockIdx.x;
    int b = t >> 9;
    int l = t & 511;
    int head = threadIdx.x >> 5;
    int lane = threadIdx.x & 31;
    int d0 = head * HD + lane;
    int base = t * D;
    int r0 = (b << 9) + ((l + 1) & 511);
    int r2 = (b << 9) + (l == 0 ? (L - 1) : 0);

    float q0 = Q[base + d0], q1 = Q[base + d0 + 32];
    const float* kp[5] = { Kh + r0 * D + d0, Kh + base + d0, Kh + r2 * D + d0,
                           Ke + base + d0,   Ks + b * D + d0 };
    const float* vp[5] = { Vh + r0 * D + d0, Vh + base + d0, Vh + r2 * D + d0,
                           Ve + base + d0,   Vs + b * D + d0 };
    float sc[5];
    #pragma unroll
    for (int i = 0; i < 5; i++) {
        float p = q0 * kp[i][0] + q1 * kp[i][32];
        #pragma unroll
        for (int o = 16; o > 0; o >>= 1) p += __shfl_xor_sync(0xffffffffu, p, o);
        sc[i] = p * 0.125f;
    }
    float m = sc[0];
    #pragma unroll
    for (int i = 1; i < 5; i++) m = fmaxf(m, sc[i]);
    float den = 0.f;
    #pragma unroll
    for (int i = 0; i < 5; i++) { sc[i] = expf(sc[i] - m); den += sc[i]; }
    float inv = 1.f / den;
    float o0 = 0.f, o1 = 0.f;
    #pragma unroll
    for (int i = 0; i < 5; i++) {
        o0 = fmaf(sc[i], vp[i][0],  o0);
        o1 = fmaf(sc[i], vp[i][32], o1);
    }
    ctx[base + d0]      = o0 * inv;
    ctx[base + d0 + 32] = o1 * inv;
}

// ---------------------------------------------------------------------------
// rel attention: 513 keys, V accumulation parallelized 4-way
// ---------------------------------------------------------------------------
__global__ void rel_attn(const float* __restrict__ Qs,  const float* __restrict__ Ksr,
                         const float* __restrict__ Kr,  const float* __restrict__ Vsr,
                         const float* __restrict__ Vr,  float* __restrict__ ctxs) {
    __shared__ float sc[513];
    __shared__ float red[256];
    __shared__ float qsh[HD];
    int b    = blockIdx.x >> 3;
    int head = blockIdx.x & 7;
    int tid  = threadIdx.x;
    int off  = head * HD;

    if (tid < HD) qsh[tid] = Qs[b * D + off + tid];
    __syncthreads();

    for (int k = tid; k < 513; k += 256) {
        const float* kv = (k == 0) ? (Ksr + b * D + off)
                                   : (Kr + ((b << 9) + k - 1) * D + off);
        float p = 0.f;
        #pragma unroll
        for (int d = 0; d < HD; d++) p = fmaf(qsh[d], kv[d], p);
        sc[k] = p * 0.125f;
    }
    __syncthreads();

    float m = -1e30f;
    for (int k = tid; k < 513; k += 256) m = fmaxf(m, sc[k]);
    red[tid] = m; __syncthreads();
    for (int st = 128; st > 0; st >>= 1) {
        if (tid < st) red[tid] = fmaxf(red[tid], red[tid + st]);
        __syncthreads();
    }
    m = red[0];
    __syncthreads();

    float dsum = 0.f;
    for (int k = tid; k < 513; k += 256) {
        float e_ = expf(sc[k] - m);
        sc[k] = e_;
        dsum += e_;
    }
    red[tid] = dsum; __syncthreads();
    for (int st = 128; st > 0; st >>= 1) {
        if (tid < st) red[tid] += red[tid + st];
        __syncthreads();
    }
    float inv = 1.f / red[0];
    __syncthreads();

    // V accumulation: thread = (group g, dim d); group g sums keys k = g, g+4, ...
    int d = tid & 63;
    int g = tid >> 6;
    float acc = 0.f;
    for (int k = g; k < 513; k += 4) {
        const float* vv = (k == 0) ? (Vsr + b * D + off)
                                   : (Vr + ((b << 9) + k - 1) * D + off);
        acc = fmaf(sc[k], vv[d], acc);
    }
    red[tid] = acc;
    __syncthreads();
    if (tid < 64) {
        float o = red[tid] + red[tid + 64] + red[tid + 128] + red[tid + 192];
        ctxs[b * D + off + tid] = o * inv;
    }
}

// ---------------------------------------------------------------------------
// relu + LayerNorm (rows of 512, eps=1e-12)
// ---------------------------------------------------------------------------
__global__ void relu_ln(const float* __restrict__ x, const float* __restrict__ w,
                        const float* __restrict__ bb, float* __restrict__ out) {
    __shared__ float red[256];
    int row = blockIdx.x;
    int tid = threadIdx.x;
    float v0 = fmaxf(x[row * D + tid],       0.f);
    float v1 = fmaxf(x[row * D + tid + 256], 0.f);
    red[tid] = v0 + v1;
    __syncthreads();
    for (int st = 128; st > 0; st >>= 1) {
        if (tid < st) red[tid] += red[tid + st];
        __syncthreads();
    }
    float mean = red[0] * (1.f / 512.f);
    __syncthreads();
    float d0 = v0 - mean, d1 = v1 - mean;
    red[tid] = d0 * d0 + d1 * d1;
    __syncthreads();
    for (int st = 128; st > 0; st >>= 1) {
        if (tid < st) red[tid] += red[tid + st];
        __syncthreads();
    }
    float inv = rsqrtf(red[0] * (1.f / 512.f) + 1e-12f);
    out[row * D + tid]       = w[tid]       * d0 * inv + bb[tid];
    out[row * D + tid + 256] = w[tid + 256] * d1 * inv + bb[tid + 256];
}

// ---------------------------------------------------------------------------
// logits = h @ ofc_w[512,17] + ofc_b
// ---------------------------------------------------------------------------
__global__ void final_logits(const float* __restrict__ h, const float* __restrict__ W,
                             const float* __restrict__ bias, float* __restrict__ out) {
    __shared__ float Wsh[512 * T];
    int tid = threadIdx.x;
    for (int i = tid; i < 512 * T; i += 256) Wsh[i] = W[i];
    __syncthreads();
    int warp = tid >> 5, lane = tid & 31;
    int row = blockIdx.x * 8 + warp;
    float acc[T];
    #pragma unroll
    for (int t = 0; t < T; t++) acc[t] = 0.f;
    const float* hr = h + row * D;
    for (int k = lane; k < D; k += 32) {
        float a = hr[k];
        #pragma unroll
        for (int t = 0; t < T; t++) acc[t] = fmaf(a, Wsh[k * T + t], acc[t]);
    }
    #pragma unroll
    for (int t = 0; t < T; t++)
        #pragma unroll
        for (int o = 16; o > 0; o >>= 1)
            acc[t] += __shfl_xor_sync(0xffffffffu, acc[t], o);
    if (lane == 0) {
        #pragma unroll
        for (int t = 0; t < T; t++) out[row * T + t] = acc[t] + bias[t];
    }
}

// ---------------------------------------------------------------------------
// Launch
// ---------------------------------------------------------------------------
extern "C" void kernel_launch(void* const* d_in, const int* in_sizes, int n_in,
                              void* d_out, int out_size) {
    (void)in_sizes; (void)n_in; (void)out_size;
    const int*   tokens  = (const int*)  d_in[0];
    const float* emb     = (const float*)d_in[4];
    const float* wsrc[8] = { (const float*)d_in[5],  (const float*)d_in[7],
                             (const float*)d_in[9],  (const float*)d_in[11],
                             (const float*)d_in[13], (const float*)d_in[15],
                             (const float*)d_in[17], (const float*)d_in[19] };
    // idx: 0 sat_q, 1 sat_k, 2 sat_v, 3 sat_o, 4 rel_q, 5 rel_k, 6 rel_v, 7 rel_o
    const float* sat_qb  = (const float*)d_in[6];
    const float* sat_kw  = (const float*)d_in[7];
    const float* sat_kb  = (const float*)d_in[8];
    const float* sat_vw  = (const float*)d_in[9];
    const float* sat_vb  = (const float*)d_in[10];
    const float* sat_ob  = (const float*)d_in[12];
    const float* rel_qw  = (const float*)d_in[13];
    const float* rel_qb  = (const float*)d_in[14];
    const float* rel_kw  = (const float*)d_in[15];
    const float* rel_kb  = (const float*)d_in[16];
    const float* rel_vw  = (const float*)d_in[17];
    const float* rel_vb  = (const float*)d_in[18];
    const float* rel_ow  = (const float*)d_in[19];
    const float* rel_ob  = (const float*)d_in[20];
    const float* ln_sw   = (const float*)d_in[21];
    const float* ln_sb   = (const float*)d_in[22];
    const float* ln_rw   = (const float*)d_in[23];
    const float* ln_rb   = (const float*)d_in[24];
    const float* ofc_w   = (const float*)d_in[25];
    const float* ofc_b   = (const float*)d_in[26];
    float* out = (float*)d_out;

    float *e, *h, *s, *q, *k, *v, *ke, *ve, *ctx, *a, *kr, *vr;
    float *ks, *vs, *qsr, *ksr, *vsr, *ctxs, *r;
    __nv_bfloat16 *ahi, *alo, *whi, *wlo;
    cudaGetSymbolAddress((void**)&e,    g_e);
    cudaGetSymbolAddress((void**)&h,    g_h);
    cudaGetSymbolAddress((void**)&s,    g_s);
    cudaGetSymbolAddress((void**)&q,    g_q);
    cudaGetSymbolAddress((void**)&k,    g_k);
    cudaGetSymbolAddress((void**)&v,    g_v);
    cudaGetSymbolAddress((void**)&ke,   g_ke);
    cudaGetSymbolAddress((void**)&ve,   g_ve);
    cudaGetSymbolAddress((void**)&ctx,  g_ctx);
    cudaGetSymbolAddress((void**)&a,    g_a);
    cudaGetSymbolAddress((void**)&kr,   g_kr);
    cudaGetSymbolAddress((void**)&vr,   g_vr);
    cudaGetSymbolAddress((void**)&ks,   g_ks);
    cudaGetSymbolAddress((void**)&vs,   g_vs);
    cudaGetSymbolAddress((void**)&qsr,  g_qsr);
    cudaGetSymbolAddress((void**)&ksr,  g_ksr);
    cudaGetSymbolAddress((void**)&vsr,  g_vsr);
    cudaGetSymbolAddress((void**)&ctxs, g_ctxs);
    cudaGetSymbolAddress((void**)&r,    g_r);
    cudaGetSymbolAddress((void**)&ahi,  g_ahi);
    cudaGetSymbolAddress((void**)&alo,  g_alo);
    cudaGetSymbolAddress((void**)&whi,  g_whi);
    cudaGetSymbolAddress((void**)&wlo,  g_wlo);

    cudaFuncSetAttribute(mma_gemm, cudaFuncAttributeMaxDynamicSharedMemorySize,
                         SMEM_BYTES);

    const float* biasTab[8] = { sat_qb, sat_kb, sat_vb, sat_ob,
                                rel_qb, rel_kb, rel_vb, rel_ob };

    dim3 gw(16, 16), bw(32, 8);
    for (int i = 0; i < 8; i++)
        wsplit<<<gw, bw>>>(wsrc[i], whi + i * DD, wlo + i * DD);

    embed_kernel<<<BL * D / 256, 256>>>(tokens, emb, e, h);
    smean_kernel<<<B * D / 256, 256>>>(e, s);

    dim3 gg(4, 64);   // 512/128 x 8192/128
    #define BIG(AIN_HI, AIN_LO, WI, OUT)                                       \
        mma_gemm<<<gg, 256, SMEM_BYTES>>>(AIN_HI, AIN_LO, whi + (WI) * DD,     \
                                          wlo + (WI) * DD, biasTab[WI], OUT)

    // e projections (e constant across cycles)
    asplit<<<BL * D / 256, 256>>>(e, ahi, alo);
    BIG(ahi, alo, 1, ke);
    BIG(ahi, alo, 2, ve);

    for (int c = 0; c < CYC; c++) {
        asplit<<<BL * D / 256, 256>>>(h, ahi, alo);
        BIG(ahi, alo, 0, q);
        BIG(ahi, alo, 1, k);
        BIG(ahi, alo, 2, v);
        sgemm16<<<8, 256>>>(s, sat_kw, sat_kb, ks);
        sgemm16<<<8, 256>>>(s, sat_vw, sat_vb, vs);

        sat_attn<<<BL, 256>>>(q, k, v, ke, ve, ks, vs, ctx);
        asplit<<<BL * D / 256, 256>>>(ctx, ahi, alo);
        BIG(ahi, alo, 3, a);
        relu_ln<<<BL, 256>>>(a, ln_sw, ln_sb, h);

        asplit<<<BL * D / 256, 256>>>(h, ahi, alo);
        BIG(ahi, alo, 5, kr);
        BIG(ahi, alo, 6, vr);
        sgemm16<<<8, 256>>>(s, rel_qw, rel_qb, qsr);
        sgemm16<<<8, 256>>>(s, rel_kw, rel_kb, ksr);
        sgemm16<<<8, 256>>>(s, rel_vw, rel_vb, vsr);

        rel_attn<<<B * NH, 256>>>(qsr, ksr, kr, vsr, vr, ctxs);
        sgemm16<<<8, 256>>>(ctxs, rel_ow, rel_ob, r);
        relu_ln<<<B, 256>>>(r, ln_rw, ln_rb, s);
    }

    final_logits<<<BL / 8, 256>>>(h, ofc_w, ofc_b, out);
}

// round 4
// speedup vs baseline: 2.0461x; 1.3711x over previous
#include <cuda_runtime.h>
#include <cuda_bf16.h>
#include <cstdint>
#include <math.h>

// Problem constants
#define B   16
#define L   512
#define D   512
#define NH  8
#define HD  64
#define T   17
#define CYC 2
#define BL  (B * L)   // 8192
#define DD  (D * D)

// ---------------------------------------------------------------------------
// Scratch (device globals)
// ---------------------------------------------------------------------------
__device__ float g_e[BL * D];
__device__ float g_h[BL * D];
__device__ float g_s[B * D];
__device__ float g_qkv[BL * 1536];   // q | k | v
__device__ float g_keve[BL * 1024];  // ke | ve
__device__ float g_krvr[BL * 1024];  // kr | vr
__device__ float g_a[BL * D];
__device__ float g_ks[B * D];
__device__ float g_vs[B * D];
__device__ float g_qsr[B * D];
__device__ float g_ksr[B * D];
__device__ float g_vsr[B * D];
__device__ float g_ctxs[B * D];
__device__ float g_r[B * D];
__device__ float g_bias[8 * D];      // concatenated biases, weight order

// bf16 split buffers (16B aligned for cp.async 16)
__device__ __align__(16) __nv_bfloat16 g_ehi[BL * D];
__device__ __align__(16) __nv_bfloat16 g_elo[BL * D];
__device__ __align__(16) __nv_bfloat16 g_hhi[BL * D];
__device__ __align__(16) __nv_bfloat16 g_hlo[BL * D];
__device__ __align__(16) __nv_bfloat16 g_cthi[BL * D];
__device__ __align__(16) __nv_bfloat16 g_ctlo[BL * D];
__device__ __align__(16) __nv_bfloat16 g_whi[8 * DD];   // transposed [N][K]
__device__ __align__(16) __nv_bfloat16 g_wlo[8 * DD];

struct Ptr8 { const float* p[8]; };
struct SJobs { const float* W[3]; const float* bias[3]; float* C[3]; };

// ---------------------------------------------------------------------------
// Embedding: e fp32 + split bf16
// ---------------------------------------------------------------------------
__global__ void embed_split(const int* __restrict__ tokens,
                            const float* __restrict__ emb,
                            float* __restrict__ e,
                            __nv_bfloat16* __restrict__ hi,
                            __nv_bfloat16* __restrict__ lo) {
    int idx = blockIdx.x * 256 + threadIdx.x;
    int row = idx / D;
    int d   = idx - row * D;
    float v = emb[tokens[row] * D + d];
    e[idx] = v;
    __nv_bfloat16 hv = __float2bfloat16_rn(v);
    hi[idx] = hv;
    lo[idx] = __float2bfloat16_rn(v - __bfloat162float(hv));
}

__global__ void smean_kernel(const float* __restrict__ e, float* __restrict__ s) {
    int idx = blockIdx.x * 256 + threadIdx.x;
    int b = idx >> 9;
    int d = idx & 511;
    const float* p = e + (b << 9) * D + d;
    float acc = 0.f;
    #pragma unroll 8
    for (int l = 0; l < L; l++) acc += p[l * D];
    s[idx] = acc * (1.f / (float)L);
}

// ---------------------------------------------------------------------------
// Weight prep: split + transpose all 8 weights; concat biases
// ---------------------------------------------------------------------------
__global__ void wsplit_all(Ptr8 W, __nv_bfloat16* __restrict__ hi,
                           __nv_bfloat16* __restrict__ lo) {
    __shared__ float t[32][33];
    const float* Wsrc = W.p[blockIdx.z];
    __nv_bfloat16* hz = hi + blockIdx.z * DD;
    __nv_bfloat16* lz = lo + blockIdx.z * DD;
    int bx = blockIdx.x, by = blockIdx.y;
    int x = threadIdx.x, y = threadIdx.y;
    #pragma unroll
    for (int j = 0; j < 32; j += 8)
        t[y + j][x] = Wsrc[(by * 32 + y + j) * 512 + bx * 32 + x];
    __syncthreads();
    #pragma unroll
    for (int j = 0; j < 32; j += 8) {
        float v = t[x][y + j];
        int n = bx * 32 + y + j;
        int k = by * 32 + x;
        __nv_bfloat16 hv = __float2bfloat16_rn(v);
        hz[n * 512 + k] = hv;
        lz[n * 512 + k] = __float2bfloat16_rn(v - __bfloat162float(hv));
    }
}

__global__ void biascat(Ptr8 bsrc, float* __restrict__ dst) {
    int i = blockIdx.x * 256 + threadIdx.x;   // 4096 threads
    dst[i] = bsrc.p[i >> 9][i & 511];
}

// ---------------------------------------------------------------------------
// Tensor-core GEMM: C[8192, N] = A[8192,512] @ Wt[N,512]^T + bias
// 3-term bf16 split; ldmatrix fragment loads; 128x128x32 tiles, 2-stage.
// ---------------------------------------------------------------------------
#define SMEM_STAGE 20480                  // bf16 elems per stage
#define SMEM_BYTES (2 * SMEM_STAGE * 2)   // 81920 B

__device__ __forceinline__ void mma16816(float* d, const uint32_t* a,
                                         const uint32_t* b) {
    asm volatile("mma.sync.aligned.m16n8k16.row.col.f32.bf16.bf16.f32 "
                 "{%0,%1,%2,%3}, {%4,%5,%6,%7}, {%8,%9}, {%0,%1,%2,%3};"
                 : "+f"(d[0]), "+f"(d[1]), "+f"(d[2]), "+f"(d[3])
                 : "r"(a[0]), "r"(a[1]), "r"(a[2]), "r"(a[3]),
                   "r"(b[0]), "r"(b[1]));
}

__device__ __forceinline__ void ldsm_x4(uint32_t* r, uint32_t a) {
    asm volatile("ldmatrix.sync.aligned.m8n8.x4.shared.b16 {%0,%1,%2,%3}, [%4];"
                 : "=r"(r[0]), "=r"(r[1]), "=r"(r[2]), "=r"(r[3]) : "r"(a));
}

__global__ void __launch_bounds__(256, 2)
mma_gemm(const __nv_bfloat16* __restrict__ Ahi, const __nv_bfloat16* __restrict__ Alo,
         const __nv_bfloat16* __restrict__ Whi, const __nv_bfloat16* __restrict__ Wlo,
         const float* __restrict__ bias, float* __restrict__ C, int ldc) {
    extern __shared__ __nv_bfloat16 sm[];
    const int tid  = threadIdx.x;
    const int lane = tid & 31;
    const int warp = tid >> 5;
    const int wm = warp >> 2;        // 0..1
    const int wn = warp & 3;         // 0..3
    const int m0 = blockIdx.y * 128;
    const int n0 = blockIdx.x * 128;

    float acc[4][4][4];
    #pragma unroll
    for (int i = 0; i < 4; i++)
        #pragma unroll
        for (int j = 0; j < 4; j++)
            #pragma unroll
            for (int t = 0; t < 4; t++) acc[i][j][t] = 0.f;

    uint32_t smbase = (uint32_t)__cvta_generic_to_shared(sm);

    auto load_stage = [&](int s, int k0) {
        uint32_t base = smbase + (uint32_t)(s * SMEM_STAGE * 2);
        #pragma unroll
        for (int i = 0; i < 2; i++) {
            int id  = tid + i * 256;
            int row = id >> 2;
            int qc  = (id & 3) << 3;
            uint32_t so = base + (uint32_t)((row * 40 + qc) * 2);
            const __nv_bfloat16* ga = Ahi + (m0 + row) * 512 + k0 + qc;
            const __nv_bfloat16* gb = Alo + (m0 + row) * 512 + k0 + qc;
            const __nv_bfloat16* gc = Whi + (n0 + row) * 512 + k0 + qc;
            const __nv_bfloat16* gd = Wlo + (n0 + row) * 512 + k0 + qc;
            asm volatile("cp.async.cg.shared.global [%0], [%1], 16;" :: "r"(so),           "l"(ga));
            asm volatile("cp.async.cg.shared.global [%0], [%1], 16;" :: "r"(so + 10240u), "l"(gb));
            asm volatile("cp.async.cg.shared.global [%0], [%1], 16;" :: "r"(so + 20480u), "l"(gc));
            asm volatile("cp.async.cg.shared.global [%0], [%1], 16;" :: "r"(so + 30720u), "l"(gd));
        }
    };

    load_stage(0, 0);
    asm volatile("cp.async.commit_group;");

    const int lrow = lane & 15;              // fragment row within 16
    const int lkoff = (lane >> 4) << 3;      // 0 or 8

    #pragma unroll 1
    for (int it = 0; it < 16; it++) {
        if (it < 15) {
            load_stage((it + 1) & 1, (it + 1) * 32);
            asm volatile("cp.async.commit_group;");
            asm volatile("cp.async.wait_group 1;");
        } else {
            asm volatile("cp.async.wait_group 0;");
        }
        __syncthreads();

        uint32_t st = smbase + (uint32_t)((it & 1) * SMEM_STAGE * 2);

        #pragma unroll
        for (int ks = 0; ks < 2; ks++) {
            int col = ks * 16 + lkoff;
            uint32_t bh[4][2], bl[4][2];
            #pragma unroll
            for (int ntp = 0; ntp < 2; ntp++) {
                int n = wn * 32 + ntp * 16 + lrow;
                uint32_t adr = st + 20480u + (uint32_t)((n * 40 + col) * 2);
                uint32_t t4[4];
                ldsm_x4(t4, adr);
                bh[ntp * 2 + 0][0] = t4[0]; bh[ntp * 2 + 0][1] = t4[2];
                bh[ntp * 2 + 1][0] = t4[1]; bh[ntp * 2 + 1][1] = t4[3];
                ldsm_x4(t4, adr + 10240u);
                bl[ntp * 2 + 0][0] = t4[0]; bl[ntp * 2 + 0][1] = t4[2];
                bl[ntp * 2 + 1][0] = t4[1]; bl[ntp * 2 + 1][1] = t4[3];
            }
            #pragma unroll
            for (int mt = 0; mt < 4; mt++) {
                int row = wm * 64 + mt * 16 + lrow;
                uint32_t adr = st + (uint32_t)((row * 40 + col) * 2);
                uint32_t ah[4], al[4];
                ldsm_x4(ah, adr);
                ldsm_x4(al, adr + 10240u);
                #pragma unroll
                for (int nt = 0; nt < 4; nt++) {
                    mma16816(acc[mt][nt], ah, bh[nt]);
                    mma16816(acc[mt][nt], ah, bl[nt]);
                    mma16816(acc[mt][nt], al, bh[nt]);
                }
            }
        }
        __syncthreads();
    }

    const int r = lane >> 2;
    const int c = (lane & 3) << 1;
    #pragma unroll
    for (int mt = 0; mt < 4; mt++) {
        #pragma unroll
        for (int nt = 0; nt < 4; nt++) {
            int row = m0 + wm * 64 + mt * 16 + r;
            int col = n0 + wn * 32 + nt * 8 + c;
            float b0 = bias[col], b1 = bias[col + 1];
            float2 v0 = make_float2(acc[mt][nt][0] + b0, acc[mt][nt][1] + b1);
            float2 v1 = make_float2(acc[mt][nt][2] + b0, acc[mt][nt][3] + b1);
            *(float2*)(C + row * ldc + col)       = v0;
            *(float2*)(C + (row + 8) * ldc + col) = v1;
        }
    }
}

// ---------------------------------------------------------------------------
// Batched small GEMM: C[16,512] = A[16,512] @ W + bias; grid (8, njobs)
// ---------------------------------------------------------------------------
__global__ void __launch_bounds__(256)
sgemm16_multi(const float* __restrict__ A, SJobs jobs) {
    __shared__ float As[16][512];
    int tid = threadIdx.x;
    for (int i = tid; i < 16 * 512; i += 256) As[i >> 9][i & 511] = A[i];
    __syncthreads();
    const float* W  = jobs.W[blockIdx.y];
    const float* bb = jobs.bias[blockIdx.y];
    float*       C  = jobs.C[blockIdx.y];
    int c  = (blockIdx.x << 6) + (tid & 63);
    int rg = (tid >> 6) << 2;
    float a0 = 0.f, a1 = 0.f, a2 = 0.f, a3 = 0.f;
    #pragma unroll 4
    for (int k = 0; k < 512; k++) {
        float w = W[k * 512 + c];
        a0 = fmaf(As[rg + 0][k], w, a0);
        a1 = fmaf(As[rg + 1][k], w, a1);
        a2 = fmaf(As[rg + 2][k], w, a2);
        a3 = fmaf(As[rg + 3][k], w, a3);
    }
    float b = bb[c];
    C[(rg + 0) * 512 + c] = a0 + b;
    C[(rg + 1) * 512 + c] = a1 + b;
    C[(rg + 2) * 512 + c] = a2 + b;
    C[(rg + 3) * 512 + c] = a3 + b;
}

// ---------------------------------------------------------------------------
// sat attention: 5 keys per token; fused bf16-split epilogue
// QKV fused [BL][1536]; keve fused [BL][1024]
// ---------------------------------------------------------------------------
__global__ void sat_attn(const float* __restrict__ QKV, const float* __restrict__ KEVE,
                         const float* __restrict__ Ks,  const float* __restrict__ Vs,
                         __nv_bfloat16* __restrict__ chi, __nv_bfloat16* __restrict__ clo) {
    int t = blockIdx.x;
    int b = t >> 9;
    int l = t & 511;
    int head = threadIdx.x >> 5;
    int lane = threadIdx.x & 31;
    int d0 = head * HD + lane;
    int r0 = (b << 9) + ((l + 1) & 511);
    int r2 = (b << 9) + (l == 0 ? (L - 1) : 0);

    const float* qp = QKV + t * 1536 + d0;
    float q0 = qp[0], q1 = qp[32];
    const float* kp[5] = { QKV + r0 * 1536 + 512 + d0, QKV + t * 1536 + 512 + d0,
                           QKV + r2 * 1536 + 512 + d0, KEVE + t * 1024 + d0,
                           Ks + b * D + d0 };
    const float* vp[5] = { QKV + r0 * 1536 + 1024 + d0, QKV + t * 1536 + 1024 + d0,
                           QKV + r2 * 1536 + 1024 + d0, KEVE + t * 1024 + 512 + d0,
                           Vs + b * D + d0 };
    float sc[5];
    #pragma unroll
    for (int i = 0; i < 5; i++) {
        float p = q0 * kp[i][0] + q1 * kp[i][32];
        #pragma unroll
        for (int o = 16; o > 0; o >>= 1) p += __shfl_xor_sync(0xffffffffu, p, o);
        sc[i] = p * 0.125f;
    }
    float m = sc[0];
    #pragma unroll
    for (int i = 1; i < 5; i++) m = fmaxf(m, sc[i]);
    float den = 0.f;
    #pragma unroll
    for (int i = 0; i < 5; i++) { sc[i] = expf(sc[i] - m); den += sc[i]; }
    float inv = 1.f / den;
    float o0 = 0.f, o1 = 0.f;
    #pragma unroll
    for (int i = 0; i < 5; i++) {
        o0 = fmaf(sc[i], vp[i][0],  o0);
        o1 = fmaf(sc[i], vp[i][32], o1);
    }
    o0 *= inv; o1 *= inv;
    int base = t * D;
    __nv_bfloat16 h0 = __float2bfloat16_rn(o0);
    __nv_bfloat16 h1 = __float2bfloat16_rn(o1);
    chi[base + d0]      = h0;
    chi[base + d0 + 32] = h1;
    clo[base + d0]      = __float2bfloat16_rn(o0 - __bfloat162float(h0));
    clo[base + d0 + 32] = __float2bfloat16_rn(o1 - __bfloat162float(h1));
}

// ---------------------------------------------------------------------------
// rel attention: 513 keys; KrVr fused [BL][1024]
// ---------------------------------------------------------------------------
__global__ void rel_attn(const float* __restrict__ Qs,  const float* __restrict__ Ksr,
                         const float* __restrict__ KrVr, const float* __restrict__ Vsr,
                         float* __restrict__ ctxs) {
    __shared__ float sc[513];
    __shared__ float red[256];
    __shared__ float qsh[HD];
    int b    = blockIdx.x >> 3;
    int head = blockIdx.x & 7;
    int tid  = threadIdx.x;
    int off  = head * HD;

    if (tid < HD) qsh[tid] = Qs[b * D + off + tid];
    __syncthreads();

    for (int k = tid; k < 513; k += 256) {
        const float* kv = (k == 0) ? (Ksr + b * D + off)
                                   : (KrVr + ((b << 9) + k - 1) * 1024 + off);
        float p = 0.f;
        #pragma unroll
        for (int d = 0; d < HD; d++) p = fmaf(qsh[d], kv[d], p);
        sc[k] = p * 0.125f;
    }
    __syncthreads();

    float m = -1e30f;
    for (int k = tid; k < 513; k += 256) m = fmaxf(m, sc[k]);
    red[tid] = m; __syncthreads();
    for (int st = 128; st > 0; st >>= 1) {
        if (tid < st) red[tid] = fmaxf(red[tid], red[tid + st]);
        __syncthreads();
    }
    m = red[0];
    __syncthreads();

    float dsum = 0.f;
    for (int k = tid; k < 513; k += 256) {
        float e_ = expf(sc[k] - m);
        sc[k] = e_;
        dsum += e_;
    }
    red[tid] = dsum; __syncthreads();
    for (int st = 128; st > 0; st >>= 1) {
        if (tid < st) red[tid] += red[tid + st];
        __syncthreads();
    }
    float inv = 1.f / red[0];
    __syncthreads();

    int d = tid & 63;
    int g = tid >> 6;
    float acc = 0.f;
    for (int k = g; k < 513; k += 4) {
        const float* vv = (k == 0) ? (Vsr + b * D + off)
                                   : (KrVr + ((b << 9) + k - 1) * 1024 + 512 + off);
        acc = fmaf(sc[k], vv[d], acc);
    }
    red[tid] = acc;
    __syncthreads();
    if (tid < 64) {
        float o = red[tid] + red[tid + 64] + red[tid + 128] + red[tid + 192];
        ctxs[b * D + off + tid] = o * inv;
    }
}

// ---------------------------------------------------------------------------
// relu + LayerNorm (+ optional bf16 split outputs)
// ---------------------------------------------------------------------------
__global__ void relu_ln(const float* __restrict__ x, const float* __restrict__ w,
                        const float* __restrict__ bb, float* __restrict__ out,
                        __nv_bfloat16* __restrict__ hi, __nv_bfloat16* __restrict__ lo) {
    __shared__ float red[256];
    int row = blockIdx.x;
    int tid = threadIdx.x;
    float v0 = fmaxf(x[row * D + tid],       0.f);
    float v1 = fmaxf(x[row * D + tid + 256], 0.f);
    red[tid] = v0 + v1;
    __syncthreads();
    for (int st = 128; st > 0; st >>= 1) {
        if (tid < st) red[tid] += red[tid + st];
        __syncthreads();
    }
    float mean = red[0] * (1.f / 512.f);
    __syncthreads();
    float d0 = v0 - mean, d1 = v1 - mean;
    red[tid] = d0 * d0 + d1 * d1;
    __syncthreads();
    for (int st = 128; st > 0; st >>= 1) {
        if (tid < st) red[tid] += red[tid + st];
        __syncthreads();
    }
    float inv = rsqrtf(red[0] * (1.f / 512.f) + 1e-12f);
    float o0 = w[tid]       * d0 * inv + bb[tid];
    float o1 = w[tid + 256] * d1 * inv + bb[tid + 256];
    out[row * D + tid]       = o0;
    out[row * D + tid + 256] = o1;
    if (hi) {
        __nv_bfloat16 h0 = __float2bfloat16_rn(o0);
        __nv_bfloat16 h1 = __float2bfloat16_rn(o1);
        hi[row * D + tid]       = h0;
        hi[row * D + tid + 256] = h1;
        lo[row * D + tid]       = __float2bfloat16_rn(o0 - __bfloat162float(h0));
        lo[row * D + tid + 256] = __float2bfloat16_rn(o1 - __bfloat162float(h1));
    }
}

// ---------------------------------------------------------------------------
// logits = h @ ofc_w[512,17] + ofc_b
// ---------------------------------------------------------------------------
__global__ void final_logits(const float* __restrict__ h, const float* __restrict__ W,
                             const float* __restrict__ bias, float* __restrict__ out) {
    __shared__ float Wsh[512 * T];
    int tid = threadIdx.x;
    for (int i = tid; i < 512 * T; i += 256) Wsh[i] = W[i];
    __syncthreads();
    int warp = tid >> 5, lane = tid & 31;
    int row = blockIdx.x * 8 + warp;
    float acc[T];
    #pragma unroll
    for (int t = 0; t < T; t++) acc[t] = 0.f;
    const float* hr = h + row * D;
    for (int k = lane; k < D; k += 32) {
        float a = hr[k];
        #pragma unroll
        for (int t = 0; t < T; t++) acc[t] = fmaf(a, Wsh[k * T + t], acc[t]);
    }
    #pragma unroll
    for (int t = 0; t < T; t++)
        #pragma unroll
        for (int o = 16; o > 0; o >>= 1)
            acc[t] += __shfl_xor_sync(0xffffffffu, acc[t], o);
    if (lane == 0) {
        #pragma unroll
        for (int t = 0; t < T; t++) out[row * T + t] = acc[t] + bias[t];
    }
}

// ---------------------------------------------------------------------------
// Launch
// ---------------------------------------------------------------------------
extern "C" void kernel_launch(void* const* d_in, const int* in_sizes, int n_in,
                              void* d_out, int out_size) {
    (void)in_sizes; (void)n_in; (void)out_size;
    const int*   tokens  = (const int*)  d_in[0];
    const float* emb     = (const float*)d_in[4];
    Ptr8 wsrc = {{ (const float*)d_in[5],  (const float*)d_in[7],
                   (const float*)d_in[9],  (const float*)d_in[11],
                   (const float*)d_in[13], (const float*)d_in[15],
                   (const float*)d_in[17], (const float*)d_in[19] }};
    Ptr8 bsrc = {{ (const float*)d_in[6],  (const float*)d_in[8],
                   (const float*)d_in[10], (const float*)d_in[12],
                   (const float*)d_in[14], (const float*)d_in[16],
                   (const float*)d_in[18], (const float*)d_in[20] }};
    const float* sat_kw = (const float*)d_in[7];
    const float* sat_kb = (const float*)d_in[8];
    const float* sat_vw = (const float*)d_in[9];
    const float* sat_vb = (const float*)d_in[10];
    const float* rel_qw = (const float*)d_in[13];
    const float* rel_qb = (const float*)d_in[14];
    const float* rel_kw = (const float*)d_in[15];
    const float* rel_kb = (const float*)d_in[16];
    const float* rel_vw = (const float*)d_in[17];
    const float* rel_vb = (const float*)d_in[18];
    const float* rel_ow = (const float*)d_in[19];
    const float* rel_ob = (const float*)d_in[20];
    const float* ln_sw  = (const float*)d_in[21];
    const float* ln_sb  = (const float*)d_in[22];
    const float* ln_rw  = (const float*)d_in[23];
    const float* ln_rb  = (const float*)d_in[24];
    const float* ofc_w  = (const float*)d_in[25];
    const float* ofc_b  = (const float*)d_in[26];
    float* out = (float*)d_out;

    float *e, *h, *s, *qkv, *keve, *krvr, *a;
    float *ks, *vs, *qsr, *ksr, *vsr, *ctxs, *r, *bias;
    __nv_bfloat16 *ehi, *elo, *hhi, *hlo, *cthi, *ctlo, *whi, *wlo;
    cudaGetSymbolAddress((void**)&e,    g_e);
    cudaGetSymbolAddress((void**)&h,    g_h);
    cudaGetSymbolAddress((void**)&s,    g_s);
    cudaGetSymbolAddress((void**)&qkv,  g_qkv);
    cudaGetSymbolAddress((void**)&keve, g_keve);
    cudaGetSymbolAddress((void**)&krvr, g_krvr);
    cudaGetSymbolAddress((void**)&a,    g_a);
    cudaGetSymbolAddress((void**)&ks,   g_ks);
    cudaGetSymbolAddress((void**)&vs,   g_vs);
    cudaGetSymbolAddress((void**)&qsr,  g_qsr);
    cudaGetSymbolAddress((void**)&ksr,  g_ksr);
    cudaGetSymbolAddress((void**)&vsr,  g_vsr);
    cudaGetSymbolAddress((void**)&ctxs, g_ctxs);
    cudaGetSymbolAddress((void**)&r,    g_r);
    cudaGetSymbolAddress((void**)&bias, g_bias);
    cudaGetSymbolAddress((void**)&ehi,  g_ehi);
    cudaGetSymbolAddress((void**)&elo,  g_elo);
    cudaGetSymbolAddress((void**)&hhi,  g_hhi);
    cudaGetSymbolAddress((void**)&hlo,  g_hlo);
    cudaGetSymbolAddress((void**)&cthi, g_cthi);
    cudaGetSymbolAddress((void**)&ctlo, g_ctlo);
    cudaGetSymbolAddress((void**)&whi,  g_whi);
    cudaGetSymbolAddress((void**)&wlo,  g_wlo);

    cudaFuncSetAttribute(mma_gemm, cudaFuncAttributeMaxDynamicSharedMemorySize,
                         SMEM_BYTES);

    // Weight prep
    wsplit_all<<<dim3(16, 16, 8), dim3(32, 8)>>>(wsrc, whi, wlo);
    biascat<<<16, 256>>>(bsrc, bias);

    embed_split<<<BL * D / 256, 256>>>(tokens, emb, e, ehi, elo);
    smean_kernel<<<B * D / 256, 256>>>(e, s);

    #define GEMM(AHI, ALO, WI, NTOT, OUT)                                      \
        mma_gemm<<<dim3((NTOT) / 128, 64), 256, SMEM_BYTES>>>(                 \
            AHI, ALO, whi + (WI) * DD, wlo + (WI) * DD, bias + (WI) * 512,     \
            OUT, NTOT)

    // e-projections: sat_k | sat_v (weights 1,2 contiguous)
    GEMM(ehi, elo, 1, 1024, keve);

    for (int c = 0; c < CYC; c++) {
        const __nv_bfloat16* chi_ = c ? hhi : ehi;
        const __nv_bfloat16* clo_ = c ? hlo : elo;

        // s-projections for sat (uses s from previous cycle)
        {
            SJobs j = {{ sat_kw, sat_vw, nullptr },
                       { sat_kb, sat_vb, nullptr },
                       { ks, vs, nullptr }};
            sgemm16_multi<<<dim3(8, 2), 256>>>(s, j);
        }

        GEMM(chi_, clo_, 0, 1536, qkv);     // q | k | v
        sat_attn<<<BL, 256>>>(qkv, keve, ks, vs, cthi, ctlo);
        GEMM(cthi, ctlo, 3, 512, a);        // sat_o
        relu_ln<<<BL, 256>>>(a, ln_sw, ln_sb, h, hhi, hlo);

        GEMM(hhi, hlo, 5, 1024, krvr);      // rel_k | rel_v
        {
            SJobs j = {{ rel_qw, rel_kw, rel_vw },
                       { rel_qb, rel_kb, rel_vb },
                       { qsr, ksr, vsr }};
            sgemm16_multi<<<dim3(8, 3), 256>>>(s, j);
        }

        rel_attn<<<B * NH, 256>>>(qsr, ksr, krvr, vsr, ctxs);
        {
            SJobs j = {{ rel_ow, nullptr, nullptr },
                       { rel_ob, nullptr, nullptr },
                       { r, nullptr, nullptr }};
            sgemm16_multi<<<dim3(8, 1), 256>>>(ctxs, j);
        }
        relu_ln<<<B, 256>>>(r, ln_rw, ln_rb, s, nullptr, nullptr);
    }

    final_logits<<<BL / 8, 256>>>(h, ofc_w, ofc_b, out);
}